// round 7
// baseline (speedup 1.0000x reference)
#include <cuda_runtime.h>
#include <cstdint>
#include <cstddef>

// ---------------------------------------------------------------------------
// RGAT layer, relation-pipelined:
//   bucket edges by relation, then for each r:
//     gemm(r) -> attn(r) -> softmax(r) -> scatter(r)
//   so h[r] (25.6 MB) stays L2-resident across its producer and all consumers.
//
// Shapes: x[50000,128] f32, W[8,128,128] f32,
//         edge_index[2,600000] i32, edge_type[600000] i32, out[50000,128] f32
// ---------------------------------------------------------------------------

#define N_NODES 50000
#define N_EDGES 600000
#define DIM     128
#define N_REL   8

// Scratch (__device__ globals: allocation-free rule)
__device__ float    g_h[(size_t)N_REL * N_NODES * DIM];   // 204.8 MB
__device__ int2     g_bsd[N_EDGES];     // (src,dst) in bucket (relation) order
__device__ float    g_battn[N_EDGES];   // attn in bucket order; then exp()
__device__ int      g_hist[N_REL];
__device__ int      g_base[N_REL + 1];
__device__ int      g_fill[N_REL];
__device__ unsigned g_relmax[N_REL];    // ordered-uint float max
__device__ float    g_relsum[N_REL];

// ---- helpers --------------------------------------------------------------

__device__ __forceinline__ unsigned f2ord(float f) {
    unsigned b = __float_as_uint(f);
    return (b & 0x80000000u) ? ~b : (b | 0x80000000u);
}
__device__ __forceinline__ float ord2f(unsigned u) {
    return (u & 0x80000000u) ? __uint_as_float(u & 0x7fffffffu)
                             : __uint_as_float(~u);
}
__device__ __forceinline__ void fma2(unsigned long long& d,
                                     unsigned long long a,
                                     unsigned long long b) {
    asm("fma.rn.f32x2 %0, %1, %2, %0;" : "+l"(d) : "l"(a), "l"(b));
}
__device__ __forceinline__ unsigned long long pk_dup(float x) {
    unsigned long long r;
    asm("mov.b64 %0, {%1, %1};" : "=l"(r) : "f"(x));
    return r;
}
__device__ __forceinline__ float2 unpk(unsigned long long v) {
    float2 f;
    asm("mov.b64 {%0, %1}, %2;" : "=f"(f.x), "=f"(f.y) : "l"(v));
    return f;
}

// ---- kernel 0: zero output + init reduction/bucket state -------------------

__global__ void init_kernel(float4* __restrict__ out) {
    int n = N_NODES * DIM / 4;
    float4 z = make_float4(0.f, 0.f, 0.f, 0.f);
    for (int i = blockIdx.x * blockDim.x + threadIdx.x; i < n;
         i += gridDim.x * blockDim.x)
        out[i] = z;
    if (blockIdx.x == 0 && threadIdx.x < N_REL) {
        g_relmax[threadIdx.x] = 0u;   // ord(-inf)
        g_relsum[threadIdx.x] = 0.f;
        g_hist[threadIdx.x]   = 0;
        g_fill[threadIdx.x]   = 0;
    }
}

// ---- bucketing: histogram -> prefix -> placement ---------------------------

__global__ void hist_kernel(const int* __restrict__ et) {
    __shared__ int s[N_REL];
    if (threadIdx.x < N_REL) s[threadIdx.x] = 0;
    __syncthreads();
    for (int e = blockIdx.x * blockDim.x + threadIdx.x; e < N_EDGES;
         e += gridDim.x * blockDim.x)
        atomicAdd(&s[et[e]], 1);
    __syncthreads();
    if (threadIdx.x < N_REL) atomicAdd(&g_hist[threadIdx.x], s[threadIdx.x]);
}

__global__ void prefix_kernel() {
    if (threadIdx.x == 0) {
        int acc = 0;
        #pragma unroll
        for (int r = 0; r < N_REL; r++) { g_base[r] = acc; acc += g_hist[r]; }
        g_base[N_REL] = acc;
    }
}

#define BK_EDGES 4096
__global__ void bucket_kernel(const int* __restrict__ ei,
                              const int* __restrict__ et) {
    __shared__ int scnt[N_REL], sbase[N_REL];
    const int tid = threadIdx.x;
    const int e0  = blockIdx.x * BK_EDGES;
    if (tid < N_REL) scnt[tid] = 0;
    __syncthreads();
    for (int i = tid; i < BK_EDGES; i += blockDim.x) {
        int e = e0 + i;
        if (e < N_EDGES) atomicAdd(&scnt[et[e]], 1);
    }
    __syncthreads();
    if (tid < N_REL) {
        sbase[tid] = g_base[tid] + atomicAdd(&g_fill[tid], scnt[tid]);
        scnt[tid]  = 0;
    }
    __syncthreads();
    for (int i = tid; i < BK_EDGES; i += blockDim.x) {
        int e = e0 + i;
        if (e < N_EDGES) {
            int t   = et[e];
            int loc = atomicAdd(&scnt[t], 1);
            g_bsd[sbase[t] + loc] = make_int2(ei[e], ei[N_EDGES + e]);
        }
    }
}

// ---- gemm: h[r] = x @ W[r], fp32 via packed f32x2 FMA ----------------------

#define BM   128
#define XST  132
#define GEMM_SMEM_BYTES ((DIM * XST + DIM * DIM) * 4)

__global__ void __launch_bounds__(256, 1)
gemm_kernel(const float* __restrict__ x, const float* __restrict__ W, int r) {
    extern __shared__ float sm[];
    float* xs = sm;              // [DIM][XST]
    float* ws = sm + DIM * XST;  // [DIM][DIM]

    const int row0 = blockIdx.x * BM;
    const int tid  = threadIdx.x;

    {
        const float4* Wv = (const float4*)(W + (size_t)r * DIM * DIM);
        float4* wsv = (float4*)ws;
        #pragma unroll
        for (int i = tid; i < DIM * DIM / 4; i += 256) wsv[i] = Wv[i];
    }
    for (int i = tid; i < BM * (DIM / 4); i += 256) {
        int row = i & (BM - 1);
        int k4  = i >> 7;
        int gr  = row0 + row;
        float4 v = (gr < N_NODES)
                 ? *(const float4*)(x + (size_t)gr * DIM + k4 * 4)
                 : make_float4(0.f, 0.f, 0.f, 0.f);
        xs[(k4 * 4 + 0) * XST + row] = v.x;
        xs[(k4 * 4 + 1) * XST + row] = v.y;
        xs[(k4 * 4 + 2) * XST + row] = v.z;
        xs[(k4 * 4 + 3) * XST + row] = v.w;
    }
    __syncthreads();

    const int ty = tid >> 4;
    const int tx = tid & 15;

    unsigned long long acc[8][4];
    #pragma unroll
    for (int i = 0; i < 8; i++)
        #pragma unroll
        for (int j = 0; j < 4; j++) acc[i][j] = 0ULL;

    const float* xrow = xs + ty * 8;
    const float* wcol = ws + tx * 8;

    #pragma unroll 4
    for (int k = 0; k < DIM; k++) {
        float4 a0 = *(const float4*)(xrow + k * XST);
        float4 a1 = *(const float4*)(xrow + k * XST + 4);
        ulonglong2 b0 = *(const ulonglong2*)(wcol + k * DIM);
        ulonglong2 b1 = *(const ulonglong2*)(wcol + k * DIM + 4);
        float av[8] = {a0.x, a0.y, a0.z, a0.w, a1.x, a1.y, a1.z, a1.w};
        #pragma unroll
        for (int i = 0; i < 8; i++) {
            unsigned long long ad = pk_dup(av[i]);
            fma2(acc[i][0], ad, b0.x);
            fma2(acc[i][1], ad, b0.y);
            fma2(acc[i][2], ad, b1.x);
            fma2(acc[i][3], ad, b1.y);
        }
    }

    float* hb = g_h + (size_t)r * N_NODES * DIM;
    #pragma unroll
    for (int i = 0; i < 8; i++) {
        int gr = row0 + ty * 8 + i;
        if (gr < N_NODES) {
            float2 p0 = unpk(acc[i][0]), p1 = unpk(acc[i][1]);
            float2 p2 = unpk(acc[i][2]), p3 = unpk(acc[i][3]);
            *(float4*)(hb + (size_t)gr * DIM + tx * 8) =
                make_float4(p0.x, p0.y, p1.x, p1.y);
            *(float4*)(hb + (size_t)gr * DIM + tx * 8 + 4) =
                make_float4(p2.x, p2.y, p3.x, p3.y);
        }
    }
}

// ---- attn(r): dot(h_src, h_dst) + leaky_relu + relation max ----------------
// Edges for relation r live at bucket positions [g_base[r], g_base[r+1]).
// h[r] slice is L2-resident (just written by gemm(r)).

__global__ void attn_kernel(int r) {
    __shared__ unsigned smax;
    const int tid = threadIdx.x;
    if (tid == 0) smax = 0u;
    __syncthreads();

    const int lo = g_base[r], hi = g_base[r + 1];
    const int lane = tid & 31;
    const int gw   = (blockIdx.x * blockDim.x + tid) >> 5;
    const int nw   = (gridDim.x * blockDim.x) >> 5;
    const float* hb = g_h + (size_t)r * N_NODES * DIM;

    for (int pos = lo + gw; pos < hi; pos += nw) {
        int2 sd = g_bsd[pos];
        const float4* hs = (const float4*)(hb + (size_t)sd.x * DIM);
        const float4* hd = (const float4*)(hb + (size_t)sd.y * DIM);
        float4 a = hs[lane];
        float4 b = hd[lane];
        float v = a.x * b.x + a.y * b.y + a.z * b.z + a.w * b.w;
        v += __shfl_xor_sync(0xffffffffu, v, 16);
        v += __shfl_xor_sync(0xffffffffu, v, 8);
        v += __shfl_xor_sync(0xffffffffu, v, 4);
        v += __shfl_xor_sync(0xffffffffu, v, 2);
        v += __shfl_xor_sync(0xffffffffu, v, 1);
        if (lane == 0) {
            v = (v > 0.f) ? v : 0.2f * v;   // leaky_relu slope 0.2
            g_battn[pos] = v;
            atomicMax(&smax, f2ord(v));
        }
    }
    __syncthreads();
    if (tid == 0) atomicMax(&g_relmax[r], smax);
}

// ---- softmax(r): exp(attn - max) in place + sum ----------------------------

__global__ void softmax_kernel(int r) {
    __shared__ float ssum;
    const int tid = threadIdx.x;
    if (tid == 0) ssum = 0.f;
    __syncthreads();

    const int lo = g_base[r], hi = g_base[r + 1];
    const float mx = ord2f(g_relmax[r]);
    float acc = 0.f;
    for (int pos = lo + blockIdx.x * blockDim.x + tid; pos < hi;
         pos += gridDim.x * blockDim.x) {
        float ex = expf(g_battn[pos] - mx);
        g_battn[pos] = ex;
        acc += ex;
    }
    acc += __shfl_xor_sync(0xffffffffu, acc, 16);
    acc += __shfl_xor_sync(0xffffffffu, acc, 8);
    acc += __shfl_xor_sync(0xffffffffu, acc, 4);
    acc += __shfl_xor_sync(0xffffffffu, acc, 2);
    acc += __shfl_xor_sync(0xffffffffu, acc, 1);
    if ((tid & 31) == 0) atomicAdd(&ssum, acc);
    __syncthreads();
    if (tid == 0) atomicAdd(&g_relsum[r], ssum);
}

// ---- scatter(r): out[dst] += (exp/denom) * h_src, vector RED ---------------

__global__ void scatter_kernel(int r, float* __restrict__ out) {
    const int tid  = threadIdx.x;
    const int lo = g_base[r], hi = g_base[r + 1];
    const float inv = 1.0f / g_relsum[r];
    const int lane = tid & 31;
    const int gw   = (blockIdx.x * blockDim.x + tid) >> 5;
    const int nw   = (gridDim.x * blockDim.x) >> 5;
    const float* hb = g_h + (size_t)r * N_NODES * DIM;

    for (int pos = lo + gw; pos < hi; pos += nw) {
        int2 sd = g_bsd[pos];
        float a = g_battn[pos] * inv;
        const float4* hs = (const float4*)(hb + (size_t)sd.x * DIM);
        float4 v = hs[lane];
        float* o = out + (size_t)sd.y * DIM + lane * 4;   // 16B aligned
        asm volatile("red.global.add.v4.f32 [%0], {%1, %2, %3, %4};"
                     :: "l"(o), "f"(v.x * a), "f"(v.y * a),
                        "f"(v.z * a), "f"(v.w * a)
                     : "memory");
    }
}

// ---- launch ----------------------------------------------------------------

extern "C" void kernel_launch(void* const* d_in, const int* in_sizes, int n_in,
                              void* d_out, int out_size) {
    const float* x  = (const float*)d_in[0];
    const float* W  = (const float*)d_in[1];
    const int*   ei = (const int*)d_in[2];
    const int*   et = (const int*)d_in[3];
    float* out = (float*)d_out;

    init_kernel<<<1024, 256>>>((float4*)out);
    hist_kernel<<<256, 256>>>(et);
    prefix_kernel<<<1, 32>>>();
    bucket_kernel<<<(N_EDGES + BK_EDGES - 1) / BK_EDGES, 256>>>(ei, et);

    cudaFuncSetAttribute(gemm_kernel,
                         cudaFuncAttributeMaxDynamicSharedMemorySize,
                         GEMM_SMEM_BYTES);
    const int gemm_blocks = (N_NODES + BM - 1) / BM;
    for (int r = 0; r < N_REL; r++) {
        gemm_kernel<<<gemm_blocks, 256, GEMM_SMEM_BYTES>>>(x, W, r);
        attn_kernel<<<592, 256>>>(r);
        softmax_kernel<<<148, 256>>>(r);
        scatter_kernel<<<592, 256>>>(r, out);
    }
}

// round 10
// speedup vs baseline: 1.2887x; 1.2887x over previous
#include <cuda_runtime.h>
#include <cstdint>
#include <cstddef>

// ---------------------------------------------------------------------------
// RGAT layer, monolithic kernels + bucket-ordered edge traversal:
//   bucket edges by relation once; attn/scatter walk them in block-contiguous
//   chunks so the ~1184 concurrently-resident CTAs span only ~2 relations
//   (~51 MB of g_h) -> L2-resident gathers, while keeping full-grid
//   parallelism (no per-relation launch serialization: that cost +172us in R7).
//
// Shapes: x[50000,128] f32, W[8,128,128] f32,
//         edge_index[2,600000] i32, edge_type[600000] i32, out[50000,128] f32
// ---------------------------------------------------------------------------

#define N_NODES 50000
#define N_EDGES 600000
#define DIM     128
#define N_REL   8

// Scratch (__device__ globals: allocation-free rule)
__device__ float    g_h[(size_t)N_REL * N_NODES * DIM];   // 204.8 MB
__device__ int2     g_bsd[N_EDGES];     // (src,dst) in relation-bucket order
__device__ float    g_battn[N_EDGES];   // attn in bucket order; then exp()
__device__ int      g_hist[N_REL];
__device__ int      g_base[N_REL + 1];
__device__ int      g_fill[N_REL];
__device__ unsigned g_relmax[N_REL];    // ordered-uint float max
__device__ float    g_relsum[N_REL];

// ---- helpers --------------------------------------------------------------

__device__ __forceinline__ unsigned f2ord(float f) {
    unsigned b = __float_as_uint(f);
    return (b & 0x80000000u) ? ~b : (b | 0x80000000u);
}
__device__ __forceinline__ float ord2f(unsigned u) {
    return (u & 0x80000000u) ? __uint_as_float(u & 0x7fffffffu)
                             : __uint_as_float(~u);
}
__device__ __forceinline__ void fma2(unsigned long long& d,
                                     unsigned long long a,
                                     unsigned long long b) {
    asm("fma.rn.f32x2 %0, %1, %2, %0;" : "+l"(d) : "l"(a), "l"(b));
}
__device__ __forceinline__ unsigned long long pk_dup(float x) {
    unsigned long long r;
    asm("mov.b64 %0, {%1, %1};" : "=l"(r) : "f"(x));
    return r;
}
__device__ __forceinline__ float2 unpk(unsigned long long v) {
    float2 f;
    asm("mov.b64 {%0, %1}, %2;" : "=f"(f.x), "=f"(f.y) : "l"(v));
    return f;
}

// ---- kernel 0: zero output + init small reduction/bucket state -------------

__global__ void init_kernel(float4* __restrict__ out) {
    int n = N_NODES * DIM / 4;
    float4 z = make_float4(0.f, 0.f, 0.f, 0.f);
    for (int i = blockIdx.x * blockDim.x + threadIdx.x; i < n;
         i += gridDim.x * blockDim.x)
        out[i] = z;
    if (blockIdx.x == 0 && threadIdx.x < N_REL) {
        g_relmax[threadIdx.x] = 0u;   // ord(-inf)
        g_relsum[threadIdx.x] = 0.f;
        g_hist[threadIdx.x]   = 0;
        g_fill[threadIdx.x]   = 0;
    }
}

// ---- bucketing: histogram -> prefix -> placement ---------------------------

__global__ void hist_kernel(const int* __restrict__ et) {
    __shared__ int s[N_REL];
    if (threadIdx.x < N_REL) s[threadIdx.x] = 0;
    __syncthreads();
    for (int e = blockIdx.x * blockDim.x + threadIdx.x; e < N_EDGES;
         e += gridDim.x * blockDim.x)
        atomicAdd(&s[et[e]], 1);
    __syncthreads();
    if (threadIdx.x < N_REL) atomicAdd(&g_hist[threadIdx.x], s[threadIdx.x]);
}

__global__ void prefix_kernel() {
    if (threadIdx.x == 0) {
        int acc = 0;
        #pragma unroll
        for (int r = 0; r < N_REL; r++) { g_base[r] = acc; acc += g_hist[r]; }
        g_base[N_REL] = acc;
    }
}

#define BK_EDGES 4096
__global__ void bucket_kernel(const int* __restrict__ ei,
                              const int* __restrict__ et) {
    __shared__ int scnt[N_REL], sbase[N_REL];
    const int tid = threadIdx.x;
    const int e0  = blockIdx.x * BK_EDGES;
    if (tid < N_REL) scnt[tid] = 0;
    __syncthreads();
    for (int i = tid; i < BK_EDGES; i += blockDim.x) {
        int e = e0 + i;
        if (e < N_EDGES) atomicAdd(&scnt[et[e]], 1);
    }
    __syncthreads();
    if (tid < N_REL) {
        sbase[tid] = g_base[tid] + atomicAdd(&g_fill[tid], scnt[tid]);
        scnt[tid]  = 0;
    }
    __syncthreads();
    for (int i = tid; i < BK_EDGES; i += blockDim.x) {
        int e = e0 + i;
        if (e < N_EDGES) {
            int t   = et[e];
            int loc = atomicAdd(&scnt[t], 1);
            g_bsd[sbase[t] + loc] = make_int2(ei[e], ei[N_EDGES + e]);
        }
    }
}

// ---- gemm: h[r] = x @ W[r], all relations in one launch (blockIdx.y = r) ---

#define BM   128
#define XST  132
#define GEMM_SMEM_BYTES ((DIM * XST + DIM * DIM) * 4)

__global__ void __launch_bounds__(256, 1)
gemm_kernel(const float* __restrict__ x, const float* __restrict__ W) {
    extern __shared__ float sm[];
    float* xs = sm;              // [DIM][XST]
    float* ws = sm + DIM * XST;  // [DIM][DIM]

    const int r    = blockIdx.y;
    const int row0 = blockIdx.x * BM;
    const int tid  = threadIdx.x;

    {
        const float4* Wv = (const float4*)(W + (size_t)r * DIM * DIM);
        float4* wsv = (float4*)ws;
        #pragma unroll
        for (int i = tid; i < DIM * DIM / 4; i += 256) wsv[i] = Wv[i];
    }
    for (int i = tid; i < BM * (DIM / 4); i += 256) {
        int row = i & (BM - 1);
        int k4  = i >> 7;
        int gr  = row0 + row;
        float4 v = (gr < N_NODES)
                 ? *(const float4*)(x + (size_t)gr * DIM + k4 * 4)
                 : make_float4(0.f, 0.f, 0.f, 0.f);
        xs[(k4 * 4 + 0) * XST + row] = v.x;
        xs[(k4 * 4 + 1) * XST + row] = v.y;
        xs[(k4 * 4 + 2) * XST + row] = v.z;
        xs[(k4 * 4 + 3) * XST + row] = v.w;
    }
    __syncthreads();

    const int ty = tid >> 4;
    const int tx = tid & 15;

    unsigned long long acc[8][4];
    #pragma unroll
    for (int i = 0; i < 8; i++)
        #pragma unroll
        for (int j = 0; j < 4; j++) acc[i][j] = 0ULL;

    const float* xrow = xs + ty * 8;
    const float* wcol = ws + tx * 8;

    #pragma unroll 4
    for (int k = 0; k < DIM; k++) {
        float4 a0 = *(const float4*)(xrow + k * XST);
        float4 a1 = *(const float4*)(xrow + k * XST + 4);
        ulonglong2 b0 = *(const ulonglong2*)(wcol + k * DIM);
        ulonglong2 b1 = *(const ulonglong2*)(wcol + k * DIM + 4);
        float av[8] = {a0.x, a0.y, a0.z, a0.w, a1.x, a1.y, a1.z, a1.w};
        #pragma unroll
        for (int i = 0; i < 8; i++) {
            unsigned long long ad = pk_dup(av[i]);
            fma2(acc[i][0], ad, b0.x);
            fma2(acc[i][1], ad, b0.y);
            fma2(acc[i][2], ad, b1.x);
            fma2(acc[i][3], ad, b1.y);
        }
    }

    float* hb = g_h + (size_t)r * N_NODES * DIM;
    #pragma unroll
    for (int i = 0; i < 8; i++) {
        int gr = row0 + ty * 8 + i;
        if (gr < N_NODES) {
            float2 p0 = unpk(acc[i][0]), p1 = unpk(acc[i][1]);
            float2 p2 = unpk(acc[i][2]), p3 = unpk(acc[i][3]);
            *(float4*)(hb + (size_t)gr * DIM + tx * 8) =
                make_float4(p0.x, p0.y, p1.x, p1.y);
            *(float4*)(hb + (size_t)gr * DIM + tx * 8 + 4) =
                make_float4(p2.x, p2.y, p3.x, p3.y);
        }
    }
}

// ---- attn: monolithic, block-contiguous chunks over bucket-ordered edges ---

#define EDGE_BLOCKS 4736
#define EDGE_CHUNK  ((N_EDGES + EDGE_BLOCKS - 1) / EDGE_BLOCKS)   // 127

__global__ void attn_kernel() {
    __shared__ int      sbase[N_REL + 1];
    __shared__ unsigned smax[N_REL];
    const int tid = threadIdx.x;
    if (tid <= N_REL) sbase[tid] = g_base[tid];
    if (tid < N_REL)  smax[tid]  = 0u;
    __syncthreads();

    const int start = blockIdx.x * EDGE_CHUNK;
    const int end   = min(start + EDGE_CHUNK, N_EDGES);
    const int lane  = tid & 31;
    const int w     = tid >> 5;            // 8 warps/block

    for (int pos = start + w; pos < end; pos += 8) {
        int2 sd = g_bsd[pos];
        int r = 0;
        #pragma unroll
        for (int i = 1; i < N_REL; i++) r += (pos >= sbase[i]);
        const float* hb = g_h + (size_t)r * N_NODES * DIM;
        const float4* hs = (const float4*)(hb + (size_t)sd.x * DIM);
        const float4* hd = (const float4*)(hb + (size_t)sd.y * DIM);
        float4 a = hs[lane];
        float4 b = hd[lane];
        float v = a.x * b.x + a.y * b.y + a.z * b.z + a.w * b.w;
        v += __shfl_xor_sync(0xffffffffu, v, 16);
        v += __shfl_xor_sync(0xffffffffu, v, 8);
        v += __shfl_xor_sync(0xffffffffu, v, 4);
        v += __shfl_xor_sync(0xffffffffu, v, 2);
        v += __shfl_xor_sync(0xffffffffu, v, 1);
        if (lane == 0) {
            v = (v > 0.f) ? v : 0.2f * v;   // leaky_relu slope 0.2
            g_battn[pos] = v;
            atomicMax(&smax[r], f2ord(v));
        }
    }
    __syncthreads();
    if (tid < N_REL && smax[tid] != 0u) atomicMax(&g_relmax[tid], smax[tid]);
}

// ---- softmax: exp(attn - max[rel]) in place + per-relation sums ------------

__global__ void softmax_kernel() {
    __shared__ int   sbase[N_REL + 1];
    __shared__ float ssum[N_REL];
    __shared__ float smx[N_REL];
    const int tid = threadIdx.x;
    if (tid <= N_REL) sbase[tid] = g_base[tid];
    if (tid < N_REL) {
        ssum[tid] = 0.f;
        smx[tid]  = ord2f(g_relmax[tid]);
    }
    __syncthreads();

    const int stride = gridDim.x * blockDim.x;
    for (int pos = blockIdx.x * blockDim.x + tid; pos < N_EDGES; pos += stride) {
        int r = 0;
        #pragma unroll
        for (int i = 1; i < N_REL; i++) r += (pos >= sbase[i]);
        float ex = expf(g_battn[pos] - smx[r]);
        g_battn[pos] = ex;
        atomicAdd(&ssum[r], ex);
    }
    __syncthreads();
    if (tid < N_REL) atomicAdd(&g_relsum[tid], ssum[tid]);
}

// ---- scatter: chunked like attn; out[dst] += (exp/denom)*h_src via RED v4 --

__global__ void scatter_kernel(float* __restrict__ out) {
    __shared__ int   sbase[N_REL + 1];
    __shared__ float sinv[N_REL];
    const int tid = threadIdx.x;
    if (tid <= N_REL) sbase[tid] = g_base[tid];
    if (tid < N_REL) {
        float s = g_relsum[tid];
        sinv[tid] = (s != 0.f) ? 1.0f / s : 0.f;
    }
    __syncthreads();

    const int start = blockIdx.x * EDGE_CHUNK;
    const int end   = min(start + EDGE_CHUNK, N_EDGES);
    const int lane  = tid & 31;
    const int w     = tid >> 5;

    for (int pos = start + w; pos < end; pos += 8) {
        int2 sd = g_bsd[pos];
        int r = 0;
        #pragma unroll
        for (int i = 1; i < N_REL; i++) r += (pos >= sbase[i]);
        float a = g_battn[pos] * sinv[r];
        const float* hb = g_h + (size_t)r * N_NODES * DIM;
        const float4* hs = (const float4*)(hb + (size_t)sd.x * DIM);
        float4 v = hs[lane];
        float* o = out + (size_t)sd.y * DIM + lane * 4;   // 16B aligned
        asm volatile("red.global.add.v4.f32 [%0], {%1, %2, %3, %4};"
                     :: "l"(o), "f"(v.x * a), "f"(v.y * a),
                        "f"(v.z * a), "f"(v.w * a)
                     : "memory");
    }
}

// ---- launch ----------------------------------------------------------------

extern "C" void kernel_launch(void* const* d_in, const int* in_sizes, int n_in,
                              void* d_out, int out_size) {
    const float* x  = (const float*)d_in[0];
    const float* W  = (const float*)d_in[1];
    const int*   ei = (const int*)d_in[2];
    const int*   et = (const int*)d_in[3];
    float* out = (float*)d_out;

    init_kernel<<<1024, 256>>>((float4*)out);
    hist_kernel<<<256, 256>>>(et);
    prefix_kernel<<<1, 32>>>();
    bucket_kernel<<<(N_EDGES + BK_EDGES - 1) / BK_EDGES, 256>>>(ei, et);

    cudaFuncSetAttribute(gemm_kernel,
                         cudaFuncAttributeMaxDynamicSharedMemorySize,
                         GEMM_SMEM_BYTES);
    dim3 gg((N_NODES + BM - 1) / BM, N_REL);
    gemm_kernel<<<gg, 256, GEMM_SMEM_BYTES>>>(x, W);

    attn_kernel<<<EDGE_BLOCKS, 256>>>();
    softmax_kernel<<<592, 256>>>();
    scatter_kernel<<<EDGE_BLOCKS, 256>>>(out);
}

// round 13
// speedup vs baseline: 1.4509x; 1.1259x over previous
#include <cuda_runtime.h>
#include <cuda_bf16.h>
#include <cstdint>
#include <cstddef>

// ---------------------------------------------------------------------------
// RGAT layer. GEMM via mma.sync.m16n8k16 bf16 split-precision (hi/lo, 4
// products, fp32 reg accum) — plain-sm_100-compatible (tcgen05 is NOT: the
// harness targets sm_100, not sm_100a; R12 ptxas proved it).
// Edge phase = round-4 form (best measured: 559.2us), bucketing dropped
// (measured net-negative in R10).
//
// Shapes: x[50000,128] f32, W[8,128,128] f32,
//         edge_index[2,600000] i32, edge_type[600000] i32, out[50000,128] f32
// ---------------------------------------------------------------------------

#define N_NODES 50000
#define N_EDGES 600000
#define DIM     128
#define N_REL   8

__device__ float    g_h[(size_t)N_REL * N_NODES * DIM];   // 204.8 MB
__device__ float    g_attn[N_EDGES];
__device__ unsigned g_relmax[N_REL];
__device__ float    g_relsum[N_REL];

// ---- helpers --------------------------------------------------------------

__device__ __forceinline__ unsigned f2ord(float f) {
    unsigned b = __float_as_uint(f);
    return (b & 0x80000000u) ? ~b : (b | 0x80000000u);
}
__device__ __forceinline__ float ord2f(unsigned u) {
    return (u & 0x80000000u) ? __uint_as_float(u & 0x7fffffffu)
                             : __uint_as_float(~u);
}

// m16n8k16 row.col bf16 MMA, fp32 accum in place.
__device__ __forceinline__ void mma_bf16(float* c,
                                         uint32_t a0, uint32_t a1,
                                         uint32_t a2, uint32_t a3,
                                         uint32_t b0, uint32_t b1) {
    asm volatile(
        "mma.sync.aligned.m16n8k16.row.col.f32.bf16.bf16.f32 "
        "{%0,%1,%2,%3}, {%4,%5,%6,%7}, {%8,%9}, {%0,%1,%2,%3};"
        : "+f"(c[0]), "+f"(c[1]), "+f"(c[2]), "+f"(c[3])
        : "r"(a0), "r"(a1), "r"(a2), "r"(a3), "r"(b0), "r"(b1));
}

// ---- kernel 0: zero output + init reduction slots --------------------------

__global__ void init_kernel(float4* __restrict__ out) {
    int n = N_NODES * DIM / 4;
    float4 z = make_float4(0.f, 0.f, 0.f, 0.f);
    for (int i = blockIdx.x * blockDim.x + threadIdx.x; i < n;
         i += gridDim.x * blockDim.x)
        out[i] = z;
    if (blockIdx.x == 0 && threadIdx.x < N_REL) {
        g_relmax[threadIdx.x] = 0u;   // ord(-inf)
        g_relsum[threadIdx.x] = 0.f;
    }
}

// ---- gemm: h[r] = x @ W[r], bf16 hi/lo split precision, mma.sync ------------
// Block: 128 rows x 128 cols, one relation (blockIdx.y). 8 warps, each owns a
// 16-row strip across all 128 cols (16 n-tiles of m16n8k16).

#define GBM 128
#define GS  136   // smem row stride in bf16 (68 words: conflict-free frags)
#define SM_A_HI 0
#define SM_A_LO (128 * GS)
#define SM_B_HI (2 * 128 * GS)
#define SM_B_LO (3 * 128 * GS)
#define GEMM_SMEM_BYTES (4 * 128 * GS * 2)

__global__ void __launch_bounds__(256, 1)
gemm_kernel(const float* __restrict__ x, const float* __restrict__ W) {
    extern __shared__ __nv_bfloat16 sm[];
    const int r    = blockIdx.y;
    const int row0 = blockIdx.x * GBM;
    const int tid  = threadIdx.x;

    // Load A = x[row0..row0+127][:], split bf16 hi/lo.
    {
        const float4* xv = (const float4*)x;
        for (int i = tid; i < GBM * (DIM / 4); i += 256) {
            int m  = i >> 5;          // row 0..127
            int c4 = i & 31;          // float4 index
            int gr = row0 + m;
            float4 v = (gr < N_NODES) ? xv[(size_t)gr * 32 + c4]
                                      : make_float4(0.f, 0.f, 0.f, 0.f);
            float vs[4] = {v.x, v.y, v.z, v.w};
            #pragma unroll
            for (int j = 0; j < 4; j++) {
                __nv_bfloat16 hi = __float2bfloat16(vs[j]);
                __nv_bfloat16 lo =
                    __float2bfloat16(vs[j] - __bfloat162float(hi));
                int o = m * GS + c4 * 4 + j;
                sm[SM_A_HI + o] = hi;
                sm[SM_A_LO + o] = lo;
            }
        }
    }
    // Load Bt[n][k] = W[r][k][n], split bf16 hi/lo (coalesced over n).
    {
        const float* Wr = W + (size_t)r * DIM * DIM;
        for (int i = tid; i < DIM * DIM; i += 256) {
            int n = i & 127;
            int k = i >> 7;
            float w = Wr[k * DIM + n];
            __nv_bfloat16 hi = __float2bfloat16(w);
            __nv_bfloat16 lo = __float2bfloat16(w - __bfloat162float(hi));
            int o = n * GS + k;
            sm[SM_B_HI + o] = hi;
            sm[SM_B_LO + o] = lo;
        }
    }
    __syncthreads();

    const int w    = tid >> 5;
    const int lane = tid & 31;
    const int qr   = lane >> 2;        // 0..7
    const int qc   = (lane & 3) * 2;   // 0,2,4,6
    const int mb   = w * 16;           // warp's m-strip

    float acc[16][4];
    #pragma unroll
    for (int t = 0; t < 16; t++)
        #pragma unroll
        for (int j = 0; j < 4; j++) acc[t][j] = 0.f;

    const __nv_bfloat16* Ah = sm + SM_A_HI;
    const __nv_bfloat16* Al = sm + SM_A_LO;
    const __nv_bfloat16* Bh = sm + SM_B_HI;
    const __nv_bfloat16* Bl = sm + SM_B_LO;

    #pragma unroll
    for (int k0 = 0; k0 < DIM; k0 += 16) {
        // A fragments (shared across all 16 n-tiles)
        const int ar0 = (mb + qr) * GS + k0 + qc;
        const int ar1 = (mb + qr + 8) * GS + k0 + qc;
        uint32_t ah0 = *(const uint32_t*)(Ah + ar0);
        uint32_t ah1 = *(const uint32_t*)(Ah + ar1);
        uint32_t ah2 = *(const uint32_t*)(Ah + ar0 + 8);
        uint32_t ah3 = *(const uint32_t*)(Ah + ar1 + 8);
        uint32_t al0 = *(const uint32_t*)(Al + ar0);
        uint32_t al1 = *(const uint32_t*)(Al + ar1);
        uint32_t al2 = *(const uint32_t*)(Al + ar0 + 8);
        uint32_t al3 = *(const uint32_t*)(Al + ar1 + 8);

        #pragma unroll
        for (int nt = 0; nt < 16; nt++) {
            const int bo = (nt * 8 + qr) * GS + k0 + qc;
            uint32_t bh0 = *(const uint32_t*)(Bh + bo);
            uint32_t bh1 = *(const uint32_t*)(Bh + bo + 8);
            uint32_t bl0 = *(const uint32_t*)(Bl + bo);
            uint32_t bl1 = *(const uint32_t*)(Bl + bo + 8);
            mma_bf16(acc[nt], ah0, ah1, ah2, ah3, bh0, bh1);
            mma_bf16(acc[nt], ah0, ah1, ah2, ah3, bl0, bl1);
            mma_bf16(acc[nt], al0, al1, al2, al3, bh0, bh1);
            mma_bf16(acc[nt], al0, al1, al2, al3, bl0, bl1);
        }
    }

    // Epilogue: c0/c1 at (mb+qr, n0+qc), c2/c3 at (mb+qr+8, n0+qc)
    float* hb = g_h + (size_t)r * N_NODES * DIM;
    const int gr0 = row0 + mb + qr;
    const int gr1 = gr0 + 8;
    #pragma unroll
    for (int nt = 0; nt < 16; nt++) {
        const int n0 = nt * 8 + qc;
        if (gr0 < N_NODES)
            *(float2*)(hb + (size_t)gr0 * DIM + n0) =
                make_float2(acc[nt][0], acc[nt][1]);
        if (gr1 < N_NODES)
            *(float2*)(hb + (size_t)gr1 * DIM + n0) =
                make_float2(acc[nt][2], acc[nt][3]);
    }
}

// ---- attn: dot(h_src, h_dst) + leaky_relu + relation max (R4 form) ----------

__global__ void attn_kernel(const int* __restrict__ ei,
                            const int* __restrict__ et) {
    __shared__ unsigned smax[N_REL];
    const int tid = threadIdx.x;
    if (tid < N_REL) smax[tid] = 0u;
    __syncthreads();

    const int lane = tid & 31;
    const int gw   = (blockIdx.x * blockDim.x + tid) >> 5;
    const int nw   = (gridDim.x * blockDim.x) >> 5;

    for (int e = gw; e < N_EDGES; e += nw) {
        int t = et[e];
        int s = ei[e];
        int d = ei[N_EDGES + e];
        const float4* hs = (const float4*)(g_h + ((size_t)t * N_NODES + s) * DIM);
        const float4* hd = (const float4*)(g_h + ((size_t)t * N_NODES + d) * DIM);
        float4 a = hs[lane];
        float4 b = hd[lane];
        float v = a.x * b.x + a.y * b.y + a.z * b.z + a.w * b.w;
        v += __shfl_xor_sync(0xffffffffu, v, 16);
        v += __shfl_xor_sync(0xffffffffu, v, 8);
        v += __shfl_xor_sync(0xffffffffu, v, 4);
        v += __shfl_xor_sync(0xffffffffu, v, 2);
        v += __shfl_xor_sync(0xffffffffu, v, 1);
        if (lane == 0) {
            v = (v > 0.f) ? v : 0.2f * v;   // leaky_relu slope 0.2
            g_attn[e] = v;
            atomicMax(&smax[t], f2ord(v));
        }
    }
    __syncthreads();
    if (tid < N_REL) atomicMax(&g_relmax[tid], smax[tid]);
}

// ---- softmax: exp(attn - max[rel]) in place + per-relation sum --------------

__global__ void softmax_kernel(const int* __restrict__ et) {
    __shared__ float ssum[N_REL];
    __shared__ float smx[N_REL];
    const int tid = threadIdx.x;
    if (tid < N_REL) {
        ssum[tid] = 0.f;
        smx[tid]  = ord2f(g_relmax[tid]);
    }
    __syncthreads();

    const int stride = gridDim.x * blockDim.x;
    for (int e = blockIdx.x * blockDim.x + tid; e < N_EDGES; e += stride) {
        int t = et[e];
        float ex = expf(g_attn[e] - smx[t]);
        g_attn[e] = ex;
        atomicAdd(&ssum[t], ex);
    }
    __syncthreads();
    if (tid < N_REL) atomicAdd(&g_relsum[tid], ssum[tid]);
}

// ---- scatter: out[dst] += (exp/denom) * h_src, vector RED (R4 form) ---------

__global__ void scatter_kernel(const int* __restrict__ ei,
                               const int* __restrict__ et,
                               float* __restrict__ out) {
    const int tid  = threadIdx.x;
    const int lane = tid & 31;
    const int gw   = (blockIdx.x * blockDim.x + tid) >> 5;
    const int nw   = (gridDim.x * blockDim.x) >> 5;

    for (int e = gw; e < N_EDGES; e += nw) {
        int t = et[e];
        int s = ei[e];
        int d = ei[N_EDGES + e];
        float a = g_attn[e] / g_relsum[t];
        const float4* hs = (const float4*)(g_h + ((size_t)t * N_NODES + s) * DIM);
        float4 v = hs[lane];
        float* o = out + (size_t)d * DIM + lane * 4;   // 16B aligned
        asm volatile("red.global.add.v4.f32 [%0], {%1, %2, %3, %4};"
                     :: "l"(o), "f"(v.x * a), "f"(v.y * a),
                        "f"(v.z * a), "f"(v.w * a)
                     : "memory");
    }
}

// ---- launch ----------------------------------------------------------------

extern "C" void kernel_launch(void* const* d_in, const int* in_sizes, int n_in,
                              void* d_out, int out_size) {
    const float* x  = (const float*)d_in[0];
    const float* W  = (const float*)d_in[1];
    const int*   ei = (const int*)d_in[2];
    const int*   et = (const int*)d_in[3];
    float* out = (float*)d_out;

    init_kernel<<<1024, 256>>>((float4*)out);

    cudaFuncSetAttribute(gemm_kernel,
                         cudaFuncAttributeMaxDynamicSharedMemorySize,
                         GEMM_SMEM_BYTES);
    dim3 gg((N_NODES + GBM - 1) / GBM, N_REL);
    gemm_kernel<<<gg, 256, GEMM_SMEM_BYTES>>>(x, W);

    attn_kernel<<<1184, 256>>>(ei, et);
    softmax_kernel<<<592, 256>>>(et);
    scatter_kernel<<<1184, 256>>>(ei, et, out);
}

// round 14
// speedup vs baseline: 1.5116x; 1.0418x over previous
#include <cuda_runtime.h>
#include <cuda_bf16.h>
#include <cstdint>
#include <cstddef>

// ---------------------------------------------------------------------------
// RGAT layer. GEMM via mma.sync.m16n8k16 bf16 split-precision, 3 products
// (ah*bh + al*bh + ah*bl; al*bl ~2^-18, dropped), ldmatrix.x4 fragment loads,
// 4m x 2n warp tiling. Edge phase = R4 form (best measured).
//
// Shapes: x[50000,128] f32, W[8,128,128] f32,
//         edge_index[2,600000] i32, edge_type[600000] i32, out[50000,128] f32
// ---------------------------------------------------------------------------

#define N_NODES 50000
#define N_EDGES 600000
#define DIM     128
#define N_REL   8

__device__ float    g_h[(size_t)N_REL * N_NODES * DIM];   // 204.8 MB
__device__ float    g_attn[N_EDGES];
__device__ unsigned g_relmax[N_REL];
__device__ float    g_relsum[N_REL];

// ---- helpers --------------------------------------------------------------

__device__ __forceinline__ unsigned f2ord(float f) {
    unsigned b = __float_as_uint(f);
    return (b & 0x80000000u) ? ~b : (b | 0x80000000u);
}
__device__ __forceinline__ float ord2f(unsigned u) {
    return (u & 0x80000000u) ? __uint_as_float(u & 0x7fffffffu)
                             : __uint_as_float(~u);
}
__device__ __forceinline__ void mma_bf16(float* c,
                                         uint32_t a0, uint32_t a1,
                                         uint32_t a2, uint32_t a3,
                                         uint32_t b0, uint32_t b1) {
    asm volatile(
        "mma.sync.aligned.m16n8k16.row.col.f32.bf16.bf16.f32 "
        "{%0,%1,%2,%3}, {%4,%5,%6,%7}, {%8,%9}, {%0,%1,%2,%3};"
        : "+f"(c[0]), "+f"(c[1]), "+f"(c[2]), "+f"(c[3])
        : "r"(a0), "r"(a1), "r"(a2), "r"(a3), "r"(b0), "r"(b1));
}
__device__ __forceinline__ void ldsm4(uint32_t& r0, uint32_t& r1,
                                      uint32_t& r2, uint32_t& r3,
                                      uint32_t addr) {
    asm volatile(
        "ldmatrix.sync.aligned.m8n8.x4.shared.b16 {%0,%1,%2,%3}, [%4];"
        : "=r"(r0), "=r"(r1), "=r"(r2), "=r"(r3) : "r"(addr));
}

// ---- kernel 0: zero output + init reduction slots --------------------------

__global__ void init_kernel(float4* __restrict__ out) {
    int n = N_NODES * DIM / 4;
    float4 z = make_float4(0.f, 0.f, 0.f, 0.f);
    for (int i = blockIdx.x * blockDim.x + threadIdx.x; i < n;
         i += gridDim.x * blockDim.x)
        out[i] = z;
    if (blockIdx.x == 0 && threadIdx.x < N_REL) {
        g_relmax[threadIdx.x] = 0u;   // ord(-inf)
        g_relsum[threadIdx.x] = 0.f;
    }
}

// ---- gemm: h[r] = x @ W[r], bf16 hi/lo, mma.sync + ldmatrix -----------------
// Block: 128x128, one relation (blockIdx.y). 8 warps as 4m x 2n:
// warp = 32 rows x 64 cols = 2 m-tiles x 8 n-tiles of m16n8k16.

#define GBM 128
#define GS  136   // smem row stride in bf16; rows 272B apart -> LDSM phase-clean
#define SM_A_HI 0
#define SM_A_LO (128 * GS)
#define SM_B_HI (2 * 128 * GS)
#define SM_B_LO (3 * 128 * GS)
#define GEMM_SMEM_BYTES (4 * 128 * GS * 2)

__global__ void __launch_bounds__(256, 1)
gemm_kernel(const float* __restrict__ x, const float* __restrict__ W) {
    extern __shared__ __nv_bfloat16 sm[];
    const int r    = blockIdx.y;
    const int row0 = blockIdx.x * GBM;
    const int tid  = threadIdx.x;

    // Load A = x[row0..row0+127][:], split bf16 hi/lo.
    {
        const float4* xv = (const float4*)x;
        for (int i = tid; i < GBM * (DIM / 4); i += 256) {
            int m  = i >> 5;
            int c4 = i & 31;
            int gr = row0 + m;
            float4 v = (gr < N_NODES) ? xv[(size_t)gr * 32 + c4]
                                      : make_float4(0.f, 0.f, 0.f, 0.f);
            float vs[4] = {v.x, v.y, v.z, v.w};
            #pragma unroll
            for (int j = 0; j < 4; j++) {
                __nv_bfloat16 hi = __float2bfloat16(vs[j]);
                __nv_bfloat16 lo =
                    __float2bfloat16(vs[j] - __bfloat162float(hi));
                int o = m * GS + c4 * 4 + j;
                sm[SM_A_HI + o] = hi;
                sm[SM_A_LO + o] = lo;
            }
        }
    }
    // Load Bt[n][k] = W[r][k][n], split bf16 hi/lo (coalesced over n).
    {
        const float* Wr = W + (size_t)r * DIM * DIM;
        for (int i = tid; i < DIM * DIM; i += 256) {
            int n = i & 127;
            int k = i >> 7;
            float w = Wr[k * DIM + n];
            __nv_bfloat16 hi = __float2bfloat16(w);
            __nv_bfloat16 lo = __float2bfloat16(w - __bfloat162float(hi));
            int o = n * GS + k;
            sm[SM_B_HI + o] = hi;
            sm[SM_B_LO + o] = lo;
        }
    }
    __syncthreads();

    const int w    = tid >> 5;
    const int lane = tid & 31;
    const int qr   = lane >> 2;        // 0..7
    const int qc   = (lane & 3) * 2;   // 0,2,4,6
    const int mb   = (w >> 1) * 32;    // warp m-origin (0,32,64,96)
    const int nb   = (w & 1) * 64;     // warp n-origin (0,64)

    // ldmatrix lane addressing: q = quadrant (matrix idx), i = row-in-matrix
    const int q = lane >> 3;           // 0..3
    const int i8 = lane & 7;           // 0..7
    const uint32_t smb = (uint32_t)__cvta_generic_to_shared(sm);
    // A: matrix q -> rows +(q&1)*8, cols +(q>>1)*8 (a0,a1,a2,a3 order)
    const uint32_t aH0 = smb + 2u * (SM_A_HI + (mb + (q & 1) * 8 + i8) * GS
                                     + (q >> 1) * 8);
    const uint32_t aH1 = aH0 + 2u * 16 * GS;          // mt=1: rows +16
    const uint32_t aL0 = aH0 + 2u * (SM_A_LO - SM_A_HI);
    const uint32_t aL1 = aL0 + 2u * 16 * GS;
    // B: matrices {bh0, bh1, bl0, bl1}: region by q>>1, col by (q&1)*8
    const uint32_t bA  = smb + 2u * (SM_B_HI + (q >> 1) * (SM_B_LO - SM_B_HI)
                                     + (nb + i8) * GS + (q & 1) * 8);

    float acc[2][8][4];
    #pragma unroll
    for (int mt = 0; mt < 2; mt++)
        #pragma unroll
        for (int nt = 0; nt < 8; nt++)
            #pragma unroll
            for (int j = 0; j < 4; j++) acc[mt][nt][j] = 0.f;

    #pragma unroll
    for (int k0 = 0; k0 < DIM; k0 += 16) {
        uint32_t ah[2][4], al[2][4];
        ldsm4(ah[0][0], ah[0][1], ah[0][2], ah[0][3], aH0 + 2u * k0);
        ldsm4(ah[1][0], ah[1][1], ah[1][2], ah[1][3], aH1 + 2u * k0);
        ldsm4(al[0][0], al[0][1], al[0][2], al[0][3], aL0 + 2u * k0);
        ldsm4(al[1][0], al[1][1], al[1][2], al[1][3], aL1 + 2u * k0);

        #pragma unroll
        for (int nt = 0; nt < 8; nt++) {
            uint32_t bh0, bh1, bl0, bl1;
            ldsm4(bh0, bh1, bl0, bl1, bA + 2u * (nt * 8 * GS + k0));
            #pragma unroll
            for (int mt = 0; mt < 2; mt++) {
                mma_bf16(acc[mt][nt], ah[mt][0], ah[mt][1], ah[mt][2],
                         ah[mt][3], bh0, bh1);
                mma_bf16(acc[mt][nt], al[mt][0], al[mt][1], al[mt][2],
                         al[mt][3], bh0, bh1);
                mma_bf16(acc[mt][nt], ah[mt][0], ah[mt][1], ah[mt][2],
                         ah[mt][3], bl0, bl1);
            }
        }
    }

    // Epilogue: c0/c1 at (row qr, col qc), c2/c3 at (row qr+8, col qc)
    float* hb = g_h + (size_t)r * N_NODES * DIM;
    #pragma unroll
    for (int mt = 0; mt < 2; mt++) {
        const int gr0 = row0 + mb + mt * 16 + qr;
        const int gr1 = gr0 + 8;
        #pragma unroll
        for (int nt = 0; nt < 8; nt++) {
            const int n0 = nb + nt * 8 + qc;
            if (gr0 < N_NODES)
                *(float2*)(hb + (size_t)gr0 * DIM + n0) =
                    make_float2(acc[mt][nt][0], acc[mt][nt][1]);
            if (gr1 < N_NODES)
                *(float2*)(hb + (size_t)gr1 * DIM + n0) =
                    make_float2(acc[mt][nt][2], acc[mt][nt][3]);
        }
    }
}

// ---- attn: dot(h_src, h_dst) + leaky_relu + relation max (R4 form) ----------

__global__ void attn_kernel(const int* __restrict__ ei,
                            const int* __restrict__ et) {
    __shared__ unsigned smax[N_REL];
    const int tid = threadIdx.x;
    if (tid < N_REL) smax[tid] = 0u;
    __syncthreads();

    const int lane = tid & 31;
    const int gw   = (blockIdx.x * blockDim.x + tid) >> 5;
    const int nw   = (gridDim.x * blockDim.x) >> 5;

    for (int e = gw; e < N_EDGES; e += nw) {
        int t = et[e];
        int s = ei[e];
        int d = ei[N_EDGES + e];
        const float4* hs = (const float4*)(g_h + ((size_t)t * N_NODES + s) * DIM);
        const float4* hd = (const float4*)(g_h + ((size_t)t * N_NODES + d) * DIM);
        float4 a = hs[lane];
        float4 b = hd[lane];
        float v = a.x * b.x + a.y * b.y + a.z * b.z + a.w * b.w;
        v += __shfl_xor_sync(0xffffffffu, v, 16);
        v += __shfl_xor_sync(0xffffffffu, v, 8);
        v += __shfl_xor_sync(0xffffffffu, v, 4);
        v += __shfl_xor_sync(0xffffffffu, v, 2);
        v += __shfl_xor_sync(0xffffffffu, v, 1);
        if (lane == 0) {
            v = (v > 0.f) ? v : 0.2f * v;   // leaky_relu slope 0.2
            g_attn[e] = v;
            atomicMax(&smax[t], f2ord(v));
        }
    }
    __syncthreads();
    if (tid < N_REL) atomicMax(&g_relmax[tid], smax[tid]);
}

// ---- softmax: exp(attn - max[rel]) in place + per-relation sum --------------

__global__ void softmax_kernel(const int* __restrict__ et) {
    __shared__ float ssum[N_REL];
    __shared__ float smx[N_REL];
    const int tid = threadIdx.x;
    if (tid < N_REL) {
        ssum[tid] = 0.f;
        smx[tid]  = ord2f(g_relmax[tid]);
    }
    __syncthreads();

    const int stride = gridDim.x * blockDim.x;
    for (int e = blockIdx.x * blockDim.x + tid; e < N_EDGES; e += stride) {
        int t = et[e];
        float ex = expf(g_attn[e] - smx[t]);
        g_attn[e] = ex;
        atomicAdd(&ssum[t], ex);
    }
    __syncthreads();
    if (tid < N_REL) atomicAdd(&g_relsum[tid], ssum[tid]);
}

// ---- scatter: out[dst] += (exp/denom) * h_src, vector RED (R4 form) ---------

__global__ void scatter_kernel(const int* __restrict__ ei,
                               const int* __restrict__ et,
                               float* __restrict__ out) {
    const int tid  = threadIdx.x;
    const int lane = tid & 31;
    const int gw   = (blockIdx.x * blockDim.x + tid) >> 5;
    const int nw   = (gridDim.x * blockDim.x) >> 5;

    for (int e = gw; e < N_EDGES; e += nw) {
        int t = et[e];
        int s = ei[e];
        int d = ei[N_EDGES + e];
        float a = g_attn[e] / g_relsum[t];
        const float4* hs = (const float4*)(g_h + ((size_t)t * N_NODES + s) * DIM);
        float4 v = hs[lane];
        float* o = out + (size_t)d * DIM + lane * 4;   // 16B aligned
        asm volatile("red.global.add.v4.f32 [%0], {%1, %2, %3, %4};"
                     :: "l"(o), "f"(v.x * a), "f"(v.y * a),
                        "f"(v.z * a), "f"(v.w * a)
                     : "memory");
    }
}

// ---- launch ----------------------------------------------------------------

extern "C" void kernel_launch(void* const* d_in, const int* in_sizes, int n_in,
                              void* d_out, int out_size) {
    const float* x  = (const float*)d_in[0];
    const float* W  = (const float*)d_in[1];
    const int*   ei = (const int*)d_in[2];
    const int*   et = (const int*)d_in[3];
    float* out = (float*)d_out;

    init_kernel<<<1024, 256>>>((float4*)out);

    cudaFuncSetAttribute(gemm_kernel,
                         cudaFuncAttributeMaxDynamicSharedMemorySize,
                         GEMM_SMEM_BYTES);
    dim3 gg((N_NODES + GBM - 1) / GBM, N_REL);
    gemm_kernel<<<gg, 256, GEMM_SMEM_BYTES>>>(x, W);

    attn_kernel<<<1184, 256>>>(ei, et);
    softmax_kernel<<<592, 256>>>(et);
    scatter_kernel<<<1184, 256>>>(ei, et, out);
}